// round 16
// baseline (speedup 1.0000x reference)
#include <cuda_runtime.h>
#include <cstddef>

#define DEVFN __device__ __forceinline__

namespace {
constexpr int Bsz  = 4096;
constexpr int Tlen = 512;
constexpr int IND  = 64;

constexpr int WT_TOTAL = 125424;
constexpr int B_TOTAL  = 912;

// state row layout (per parity): x[0,64) h1[64,154) h2[154,220) h3[220,268) h4[268,292)
constexpr int SROWS = 292;
constexpr int SDIM  = 36;                      // 144B rows, 16B aligned
constexpr int PSTRIDE = SROWS * SDIM;          // 10512 floats per parity
constexpr int MTILE = 32;
constexpr int NTHREADS = 512;
constexpr int NBLOCKS  = Bsz / MTILE;          // 128
constexpr int NSTAGES  = Tlen + 3;             // 515

// smem layout (float offsets): parity0 | parity1 | WL2 | WL3
constexpr int WL2_OFF = 2 * PSTRIDE;           // 21024
constexpr int WL3_OFF = WL2_OFF + 21888;       // 42912
constexpr int SMEM_FLOATS = WL3_OFF + 6912;    // 49824
constexpr int SMEM_BYTES  = SMEM_FLOATS * 4;   // 199296 B (< 227KB)

constexpr int H4OFF = 268;
}

// Weights, gate-interleaved: g_WT[(k*HH + j)*4 + g] per layer block; g in {i,f,g,o}
__device__ __align__(16) float g_WT[WT_TOTAL];
__device__ float g_Bias[B_TOTAL];

// ---------------------------------------------------------------------------
// Prep kernel: transpose to gate-interleaved [k][j][4] layout, fuse biases.
// ---------------------------------------------------------------------------
__global__ void prep_kernel(
    const float* __restrict__ Wih1, const float* __restrict__ Whh1,
    const float* __restrict__ bih1, const float* __restrict__ bhh1,
    const float* __restrict__ Wih2, const float* __restrict__ Whh2,
    const float* __restrict__ bih2, const float* __restrict__ bhh2,
    const float* __restrict__ Wih3, const float* __restrict__ Whh3,
    const float* __restrict__ bih3, const float* __restrict__ bhh3,
    const float* __restrict__ Wih4, const float* __restrict__ Whh4,
    const float* __restrict__ bih4, const float* __restrict__ bhh4)
{
    const float* Wih[4] = {Wih1, Wih2, Wih3, Wih4};
    const float* Whh[4] = {Whh1, Whh2, Whh3, Whh4};
    const float* bih[4] = {bih1, bih2, bih3, bih4};
    const float* bhh[4] = {bhh1, bhh2, bhh3, bhh4};

    const int lH[4]    = {90, 66, 48, 24};
    const int lDIN[4]  = {64, 90, 66, 48};
    const int lWOFF[4] = {0, 55440, 96624, 118512};
    const int lBOFF[4] = {0, 360, 624, 816};

    int idx = blockIdx.x * blockDim.x + threadIdx.x;
    if (idx < WT_TOTAL) {
        int l = (idx < lWOFF[1]) ? 0 : (idx < lWOFF[2]) ? 1 : (idx < lWOFF[3]) ? 2 : 3;
        int r  = idx - lWOFF[l];
        int f4 = r >> 2;
        int g  = r & 3;
        int k  = f4 / lH[l];
        int j  = f4 % lH[l];
        int n  = g * lH[l] + j;
        float v;
        if (k < lDIN[l]) v = Wih[l][n * lDIN[l] + k];
        else             v = Whh[l][n * lH[l] + (k - lDIN[l])];
        g_WT[idx] = v;
    } else if (idx < WT_TOTAL + B_TOTAL) {
        int bi = idx - WT_TOTAL;
        int l = (bi < lBOFF[1]) ? 0 : (bi < lBOFF[2]) ? 1 : (bi < lBOFF[3]) ? 2 : 3;
        int n = bi - lBOFF[l];
        g_Bias[bi] = bih[l][n] + bhh[l][n];
    }
}

// ---------------------------------------------------------------------------
// f32x2 helpers
// ---------------------------------------------------------------------------
DEVFN unsigned long long pk2(float lo, float hi) {
    unsigned long long u;
    asm("mov.b64 %0, {%1, %2};" : "=l"(u) : "f"(lo), "f"(hi));
    return u;
}
DEVFN float2 un2(unsigned long long u) {
    float2 v;
    asm("mov.b64 {%0, %1}, %2;" : "=f"(v.x), "=f"(v.y) : "l"(u));
    return v;
}
DEVFN void fma2(unsigned long long& d, unsigned long long a, unsigned long long b) {
    asm("fma.rn.f32x2 %0, %1, %2, %0;" : "+l"(d) : "l"(a), "l"(b));
}
DEVFN float sigf(float x)     { return __fdividef(1.0f, 1.0f + __expf(-x)); }
DEVFN float tanhfast(float x) { return __fdividef(2.0f, 1.0f + __expf(-2.0f * x)) - 1.0f; }

// one k-step of the gates GEMM (32 FFMA2)
DEVFN void kstep(unsigned long long acc[4][8], const ulonglong2* pa,
                 int k, float4 wv)
{
    ulonglong2 q0 = pa[k * 9 + 0];
    ulonglong2 q1 = pa[k * 9 + 1];
    ulonglong2 q2 = pa[k * 9 + 2];
    ulonglong2 q3 = pa[k * 9 + 3];
    unsigned long long p0 = pk2(wv.x, wv.x);
    unsigned long long p1 = pk2(wv.y, wv.y);
    unsigned long long p2 = pk2(wv.z, wv.z);
    unsigned long long p3 = pk2(wv.w, wv.w);
    fma2(acc[0][0], q0.x, p0); fma2(acc[0][1], q0.y, p0);
    fma2(acc[0][2], q1.x, p0); fma2(acc[0][3], q1.y, p0);
    fma2(acc[0][4], q2.x, p0); fma2(acc[0][5], q2.y, p0);
    fma2(acc[0][6], q3.x, p0); fma2(acc[0][7], q3.y, p0);
    fma2(acc[1][0], q0.x, p1); fma2(acc[1][1], q0.y, p1);
    fma2(acc[1][2], q1.x, p1); fma2(acc[1][3], q1.y, p1);
    fma2(acc[1][4], q2.x, p1); fma2(acc[1][5], q2.y, p1);
    fma2(acc[1][6], q3.x, p1); fma2(acc[1][7], q3.y, p1);
    fma2(acc[2][0], q0.x, p2); fma2(acc[2][1], q0.y, p2);
    fma2(acc[2][2], q1.x, p2); fma2(acc[2][3], q1.y, p2);
    fma2(acc[2][4], q2.x, p2); fma2(acc[2][5], q2.y, p2);
    fma2(acc[2][6], q3.x, p2); fma2(acc[2][7], q3.y, p2);
    fma2(acc[3][0], q0.x, p3); fma2(acc[3][1], q0.y, p3);
    fma2(acc[3][2], q1.x, p3); fma2(acc[3][3], q1.y, p3);
    fma2(acc[3][4], q2.x, p3); fma2(acc[3][5], q2.y, p3);
    fma2(acc[3][6], q3.x, p3); fma2(acc[3][7], q3.y, p3);
}

// ---------------------------------------------------------------------------
// One layer-stage for one thread: gates GEMM over KK inputs + cell update.
// Thread owns unit j, batch half [half*16, half*16+16) = 8 f32x2 pairs.
// GL path: 4-deep register prefetch with STATIC indices, primed per stage.
// Lookahead = 4 k-iters (~2x the L2 latency at 4-warp contention).  Overreads
// at k = KK..KK+3 stay inside g_WT (values never used): L0 max float4 index
// j+157*90 < 31356, L1 max 13860+j+159*66 < 31356.
// ---------------------------------------------------------------------------
template <int HH, int KK, int SO, int HO, bool GL>
DEVFN void do_layer(float4 bias, const float4* __restrict__ wj,
                    const float* pin, float* pout,
                    unsigned long long* c, int j, int half)
{
    unsigned long long acc[4][8];
#pragma unroll
    for (int p = 0; p < 8; ++p) {
        acc[0][p] = pk2(bias.x, bias.x);
        acc[1][p] = pk2(bias.y, bias.y);
        acc[2][p] = pk2(bias.z, bias.z);
        acc[3][p] = pk2(bias.w, bias.w);
    }

    const ulonglong2* pa =
        reinterpret_cast<const ulonglong2*>(pin) + SO * 9 + half * 4;

    static_assert((KK & 1) == 0, "KK must be even");

    if (GL) {
        float4 wb0 = __ldg(wj);
        float4 wb1 = __ldg(wj + HH);
        float4 wb2 = __ldg(wj + 2 * HH);
        float4 wb3 = __ldg(wj + 3 * HH);
#pragma unroll 2
        for (int kb = 0; kb < KK / 2; ++kb) {
            const int k0 = 2 * kb;
            float4 wv0 = wb0;
            float4 wv1 = wb1;
            wb0 = wb2;
            wb1 = wb3;
            wb2 = __ldg(wj + (k0 + 4) * HH);
            wb3 = __ldg(wj + (k0 + 5) * HH);
            kstep(acc, pa, k0, wv0);
            kstep(acc, pa, k0 + 1, wv1);
        }
    } else {
#pragma unroll 4
        for (int k = 0; k < KK; ++k)
            kstep(acc, pa, k, wj[k * HH]);
    }

    float hn[16];
#pragma unroll
    for (int p = 0; p < 8; ++p) {
        float2 iv = un2(acc[0][p]);
        float2 fv = un2(acc[1][p]);
        float2 gv = un2(acc[2][p]);
        float2 ov = un2(acc[3][p]);
        float2 cv = un2(c[p]);
        float c0 = sigf(fv.x) * cv.x + sigf(iv.x) * tanhfast(gv.x);
        float c1 = sigf(fv.y) * cv.y + sigf(iv.y) * tanhfast(gv.y);
        c[p] = pk2(c0, c1);
        hn[2 * p]     = sigf(ov.x) * tanhfast(c0);
        hn[2 * p + 1] = sigf(ov.y) * tanhfast(c1);
    }
    float* hp = pout + (HO + j) * SDIM + half * 16;
    *reinterpret_cast<float4*>(hp)      = *reinterpret_cast<const float4*>(hn);
    *reinterpret_cast<float4*>(hp + 4)  = *reinterpret_cast<const float4*>(hn + 4);
    *reinterpret_cast<float4*>(hp + 8)  = *reinterpret_cast<const float4*>(hn + 8);
    *reinterpret_cast<float4*>(hp + 12) = *reinterpret_cast<const float4*>(hn + 12);
}

// ---------------------------------------------------------------------------
// Persistent main kernel: one CTA = 32 batch rows; layers software-pipelined
// over stages (L_l at stage s handles timestep s-l).  One barrier per stage.
// ---------------------------------------------------------------------------
__global__ void __launch_bounds__(NTHREADS, 1)
lstm_main(const float* __restrict__ x,
          const float* __restrict__ fcw,
          const float* __restrict__ fcb,
          float* __restrict__ out)
{
    extern __shared__ float sm[];

    const int tid  = threadIdx.x;
    const int w    = tid >> 5;
    const int lane = tid & 31;
    const int b0   = blockIdx.x * MTILE;

    // warp -> (layer, local index): balances FFMA2 load across SMSPs
    const int wlayerA[16] = {1,0,0,0, 1,0,0,0, 2,1,1,1, 3,2,3,2};
    const int wlocA[16]   = {0,0,1,2, 1,3,4,5, 0,2,3,4, 0,1,1,2};
    const int lyr = wlayerA[w];
    const int loc = wlocA[w];
    const int j    = loc * 16 + (lane >> 1);
    const int half = lane & 1;

    const int HHt[4] = {90, 66, 48, 24};
    const int BOt[4] = {0, 360, 624, 816};
    const int HH = HHt[lyr];
    const bool on = (j < HH);

    float4 bias = make_float4(0.f, 0.f, 0.f, 0.f);
    if (on) {
        const int BO = BOt[lyr];
        bias = make_float4(g_Bias[BO + j], g_Bias[BO + HH + j],
                           g_Bias[BO + 2 * HH + j], g_Bias[BO + 3 * HH + j]);
    }

    // stage L2/L3 weights into smem
    {
        const float4* gw4 = reinterpret_cast<const float4*>(g_WT);
        float4* w2 = reinterpret_cast<float4*>(sm + WL2_OFF);
        float4* w3 = reinterpret_cast<float4*>(sm + WL3_OFF);
        for (int i = tid; i < 5472; i += NTHREADS) w2[i] = gw4[24156 + i];
        for (int i = tid; i < 1728; i += NTHREADS) w3[i] = gw4[29628 + i];
    }
    // zero both state parities
    for (int i = tid; i < 2 * PSTRIDE; i += NTHREADS) sm[i] = 0.0f;

    // weight pointer for this thread's layer (float4 units, element k at wj[k*HH])
    const float4* gw = reinterpret_cast<const float4*>(g_WT);
    const float4* wj;
    if      (lyr == 0) wj = gw + j;
    else if (lyr == 1) wj = gw + 13860 + j;
    else if (lyr == 2) wj = reinterpret_cast<const float4*>(sm + WL2_OFF) + j;
    else               wj = reinterpret_cast<const float4*>(sm + WL3_OFF) + j;

    // stage x[0] into parity 1 (read by L0 at stage 0)
    const float* xrow = x + (size_t)(b0 + lane) * Tlen * IND + 4 * w;
    {
        float4 xv = *reinterpret_cast<const float4*>(xrow);
        float* p1 = sm + PSTRIDE;
        p1[(4 * w + 0) * SDIM + lane] = xv.x;
        p1[(4 * w + 1) * SDIM + lane] = xv.y;
        p1[(4 * w + 2) * SDIM + lane] = xv.z;
        p1[(4 * w + 3) * SDIM + lane] = xv.w;
    }
    __syncthreads();

    unsigned long long c[8];
#pragma unroll
    for (int p = 0; p < 8; ++p) c[p] = 0ull;

    for (int s = 0; s < NSTAGES; ++s) {
        const float* pin  = sm + ((s + 1) & 1) * PSTRIDE;  // == (s-1)&1
        float*       pout = sm + (s & 1) * PSTRIDE;

        // prefetch next x tile (goes to pout's x rows: parity s&1 read at s+1)
        float4 xv;
        const bool stx = (s < Tlen - 1);
        if (stx) xv = *reinterpret_cast<const float4*>(xrow + (size_t)(s + 1) * IND);

        const bool act = on && (s >= lyr) && (s - lyr < Tlen);
        if (act) {
            if      (lyr == 0) do_layer<90, 154,   0,  64, true >(bias, wj, pin, pout, c, j, half);
            else if (lyr == 1) do_layer<66, 156,  64, 154, true >(bias, wj, pin, pout, c, j, half);
            else if (lyr == 2) do_layer<48, 114, 154, 220, false>(bias, wj, pin, pout, c, j, half);
            else               do_layer<24,  72, 220, 268, false>(bias, wj, pin, pout, c, j, half);
        }

        if (stx) {
            pout[(4 * w + 0) * SDIM + lane] = xv.x;
            pout[(4 * w + 1) * SDIM + lane] = xv.y;
            pout[(4 * w + 2) * SDIM + lane] = xv.z;
            pout[(4 * w + 3) * SDIM + lane] = xv.w;
        }
        __syncthreads();
    }

    // h4[T-1] written at stage 514 -> parity 0
    if (tid < 32) {
        float acc = fcb[0];
#pragma unroll
        for (int jj = 0; jj < 24; ++jj)
            acc += sm[(H4OFF + jj) * SDIM + tid] * fcw[jj];
        out[b0 + tid] = acc;
    }
}

// ---------------------------------------------------------------------------
extern "C" void kernel_launch(void* const* d_in, const int* in_sizes, int n_in,
                              void* d_out, int out_size)
{
    (void)in_sizes; (void)n_in; (void)out_size;
    const float* x    = (const float*)d_in[0];
    const float* Wih1 = (const float*)d_in[1];
    const float* Whh1 = (const float*)d_in[2];
    const float* bih1 = (const float*)d_in[3];
    const float* bhh1 = (const float*)d_in[4];
    const float* Wih2 = (const float*)d_in[5];
    const float* Whh2 = (const float*)d_in[6];
    const float* bih2 = (const float*)d_in[7];
    const float* bhh2 = (const float*)d_in[8];
    const float* Wih3 = (const float*)d_in[9];
    const float* Whh3 = (const float*)d_in[10];
    const float* bih3 = (const float*)d_in[11];
    const float* bhh3 = (const float*)d_in[12];
    const float* Wih4 = (const float*)d_in[13];
    const float* Whh4 = (const float*)d_in[14];
    const float* bih4 = (const float*)d_in[15];
    const float* bhh4 = (const float*)d_in[16];
    const float* fcw  = (const float*)d_in[17];
    const float* fcb  = (const float*)d_in[18];

    static bool attr_done = false;
    if (!attr_done) {
        cudaFuncSetAttribute(lstm_main,
                             cudaFuncAttributeMaxDynamicSharedMemorySize,
                             SMEM_BYTES);
        attr_done = true;
    }

    const int prep_total = WT_TOTAL + B_TOTAL;
    prep_kernel<<<(prep_total + 255) / 256, 256>>>(
        Wih1, Whh1, bih1, bhh1, Wih2, Whh2, bih2, bhh2,
        Wih3, Whh3, bih3, bhh3, Wih4, Whh4, bih4, bhh4);

    lstm_main<<<NBLOCKS, NTHREADS, SMEM_BYTES>>>(x, fcw, fcb, (float*)d_out);
}

// round 17
// speedup vs baseline: 1.2218x; 1.2218x over previous
#include <cuda_runtime.h>
#include <cstddef>

#define DEVFN __device__ __forceinline__

namespace {
constexpr int Bsz  = 4096;
constexpr int Tlen = 512;
constexpr int IND  = 64;

constexpr int WT_TOTAL = 125424;
constexpr int B_TOTAL  = 912;

// state row layout (per parity): x[0,64) h1[64,154) h2[154,220) h3[220,268) h4[268,292)
constexpr int SROWS = 292;
constexpr int SDIM  = 32;                      // 128B rows; halves at cols 0..13 and 16..29
constexpr int PSTRIDE = SROWS * SDIM;          // 9344 floats per parity
constexpr int MTILE = 28;                      // batch rows per CTA
constexpr int NTHREADS = 512;
constexpr int NBLOCKS  = 147;                  // ceil(4096/28); one wave on 148 SMs
constexpr int NSTAGES  = Tlen + 3;             // 515
constexpr int NPAIR = 7;                       // f32x2 pairs per thread (14 rows/half)

// smem layout (float offsets): parity0 | parity1 | WL2 | WL3
constexpr int WL2_OFF = 2 * PSTRIDE;           // 18688
constexpr int WL3_OFF = WL2_OFF + 21888;       // 40576
constexpr int SMEM_FLOATS = WL3_OFF + 6912;    // 47488
constexpr int SMEM_BYTES  = SMEM_FLOATS * 4;   // 189952 B (< 227KB)

constexpr int H4OFF = 268;
}

// Weights, gate-interleaved: g_WT[(k*HH + j)*4 + g] per layer block; g in {i,f,g,o}
__device__ __align__(16) float g_WT[WT_TOTAL];
__device__ float g_Bias[B_TOTAL];

// ---------------------------------------------------------------------------
// Prep kernel: transpose to gate-interleaved [k][j][4] layout, fuse biases.
// ---------------------------------------------------------------------------
__global__ void prep_kernel(
    const float* __restrict__ Wih1, const float* __restrict__ Whh1,
    const float* __restrict__ bih1, const float* __restrict__ bhh1,
    const float* __restrict__ Wih2, const float* __restrict__ Whh2,
    const float* __restrict__ bih2, const float* __restrict__ bhh2,
    const float* __restrict__ Wih3, const float* __restrict__ Whh3,
    const float* __restrict__ bih3, const float* __restrict__ bhh3,
    const float* __restrict__ Wih4, const float* __restrict__ Whh4,
    const float* __restrict__ bih4, const float* __restrict__ bhh4)
{
    const float* Wih[4] = {Wih1, Wih2, Wih3, Wih4};
    const float* Whh[4] = {Whh1, Whh2, Whh3, Whh4};
    const float* bih[4] = {bih1, bih2, bih3, bih4};
    const float* bhh[4] = {bhh1, bhh2, bhh3, bhh4};

    const int lH[4]    = {90, 66, 48, 24};
    const int lDIN[4]  = {64, 90, 66, 48};
    const int lWOFF[4] = {0, 55440, 96624, 118512};
    const int lBOFF[4] = {0, 360, 624, 816};

    int idx = blockIdx.x * blockDim.x + threadIdx.x;
    if (idx < WT_TOTAL) {
        int l = (idx < lWOFF[1]) ? 0 : (idx < lWOFF[2]) ? 1 : (idx < lWOFF[3]) ? 2 : 3;
        int r  = idx - lWOFF[l];
        int f4 = r >> 2;
        int g  = r & 3;
        int k  = f4 / lH[l];
        int j  = f4 % lH[l];
        int n  = g * lH[l] + j;
        float v;
        if (k < lDIN[l]) v = Wih[l][n * lDIN[l] + k];
        else             v = Whh[l][n * lH[l] + (k - lDIN[l])];
        g_WT[idx] = v;
    } else if (idx < WT_TOTAL + B_TOTAL) {
        int bi = idx - WT_TOTAL;
        int l = (bi < lBOFF[1]) ? 0 : (bi < lBOFF[2]) ? 1 : (bi < lBOFF[3]) ? 2 : 3;
        int n = bi - lBOFF[l];
        g_Bias[bi] = bih[l][n] + bhh[l][n];
    }
}

// ---------------------------------------------------------------------------
// f32x2 helpers
// ---------------------------------------------------------------------------
DEVFN unsigned long long pk2(float lo, float hi) {
    unsigned long long u;
    asm("mov.b64 %0, {%1, %2};" : "=l"(u) : "f"(lo), "f"(hi));
    return u;
}
DEVFN float2 un2(unsigned long long u) {
    float2 v;
    asm("mov.b64 {%0, %1}, %2;" : "=f"(v.x), "=f"(v.y) : "l"(u));
    return v;
}
DEVFN void fma2(unsigned long long& d, unsigned long long a, unsigned long long b) {
    asm("fma.rn.f32x2 %0, %1, %2, %0;" : "+l"(d) : "l"(a), "l"(b));
}
DEVFN float sigf(float x)     { return __fdividef(1.0f, 1.0f + __expf(-x)); }
DEVFN float tanhfast(float x) { return __fdividef(2.0f, 1.0f + __expf(-2.0f * x)) - 1.0f; }

// one k-step of the gates GEMM (28 FFMA2): 7 pairs = 3x LDS.128 + 1x LDS.64
DEVFN void kstep(unsigned long long acc[4][NPAIR],
                 const unsigned long long* pa, int k, float4 wv)
{
    const unsigned long long* row = pa + k * (SDIM / 2);
    ulonglong2 u0 = *reinterpret_cast<const ulonglong2*>(row);
    ulonglong2 u1 = *reinterpret_cast<const ulonglong2*>(row + 2);
    ulonglong2 u2 = *reinterpret_cast<const ulonglong2*>(row + 4);
    unsigned long long q6 = row[6];
    unsigned long long p0 = pk2(wv.x, wv.x);
    unsigned long long p1 = pk2(wv.y, wv.y);
    unsigned long long p2 = pk2(wv.z, wv.z);
    unsigned long long p3 = pk2(wv.w, wv.w);
    fma2(acc[0][0], u0.x, p0); fma2(acc[0][1], u0.y, p0);
    fma2(acc[0][2], u1.x, p0); fma2(acc[0][3], u1.y, p0);
    fma2(acc[0][4], u2.x, p0); fma2(acc[0][5], u2.y, p0);
    fma2(acc[0][6], q6,   p0);
    fma2(acc[1][0], u0.x, p1); fma2(acc[1][1], u0.y, p1);
    fma2(acc[1][2], u1.x, p1); fma2(acc[1][3], u1.y, p1);
    fma2(acc[1][4], u2.x, p1); fma2(acc[1][5], u2.y, p1);
    fma2(acc[1][6], q6,   p1);
    fma2(acc[2][0], u0.x, p2); fma2(acc[2][1], u0.y, p2);
    fma2(acc[2][2], u1.x, p2); fma2(acc[2][3], u1.y, p2);
    fma2(acc[2][4], u2.x, p2); fma2(acc[2][5], u2.y, p2);
    fma2(acc[2][6], q6,   p2);
    fma2(acc[3][0], u0.x, p3); fma2(acc[3][1], u0.y, p3);
    fma2(acc[3][2], u1.x, p3); fma2(acc[3][3], u1.y, p3);
    fma2(acc[3][4], u2.x, p3); fma2(acc[3][5], u2.y, p3);
    fma2(acc[3][6], q6,   p3);
}

// ---------------------------------------------------------------------------
// One layer-stage for one thread: gates GEMM over KK inputs + cell update.
// Thread owns unit j, batch half (14 rows at float cols half*16 .. +13).
// GL path: 2-deep register prefetch (R11 schedule — best measured).
// Overreads at k = KK..KK+1 stay inside g_WT (values never used).
// ---------------------------------------------------------------------------
template <int HH, int KK, int SO, int HO, bool GL>
DEVFN void do_layer(float4 bias, const float4* __restrict__ wj,
                    const float* pin, float* pout,
                    unsigned long long* c, int j, int half)
{
    unsigned long long acc[4][NPAIR];
#pragma unroll
    for (int p = 0; p < NPAIR; ++p) {
        acc[0][p] = pk2(bias.x, bias.x);
        acc[1][p] = pk2(bias.y, bias.y);
        acc[2][p] = pk2(bias.z, bias.z);
        acc[3][p] = pk2(bias.w, bias.w);
    }

    const unsigned long long* pa =
        reinterpret_cast<const unsigned long long*>(pin) + SO * (SDIM / 2) + half * 8;

    static_assert((KK & 1) == 0, "KK must be even");

    if (GL) {
        float4 wb0 = __ldg(wj);
        float4 wb1 = __ldg(wj + HH);
#pragma unroll 2
        for (int kb = 0; kb < KK / 2; ++kb) {
            const int k0 = 2 * kb;
            float4 wv0 = wb0;
            float4 wv1 = wb1;
            wb0 = __ldg(wj + (k0 + 2) * HH);
            wb1 = __ldg(wj + (k0 + 3) * HH);
            kstep(acc, pa, k0, wv0);
            kstep(acc, pa, k0 + 1, wv1);
        }
    } else {
#pragma unroll 4
        for (int k = 0; k < KK; ++k)
            kstep(acc, pa, k, wj[k * HH]);
    }

    float hn[2 * NPAIR];
#pragma unroll
    for (int p = 0; p < NPAIR; ++p) {
        float2 iv = un2(acc[0][p]);
        float2 fv = un2(acc[1][p]);
        float2 gv = un2(acc[2][p]);
        float2 ov = un2(acc[3][p]);
        float2 cv = un2(c[p]);
        float c0 = sigf(fv.x) * cv.x + sigf(iv.x) * tanhfast(gv.x);
        float c1 = sigf(fv.y) * cv.y + sigf(iv.y) * tanhfast(gv.y);
        c[p] = pk2(c0, c1);
        hn[2 * p]     = sigf(ov.x) * tanhfast(c0);
        hn[2 * p + 1] = sigf(ov.y) * tanhfast(c1);
    }
    float* hp = pout + (HO + j) * SDIM + half * 16;
    *reinterpret_cast<float4*>(hp)      = *reinterpret_cast<const float4*>(hn);
    *reinterpret_cast<float4*>(hp + 4)  = *reinterpret_cast<const float4*>(hn + 4);
    *reinterpret_cast<float4*>(hp + 8)  = *reinterpret_cast<const float4*>(hn + 8);
    *reinterpret_cast<float2*>(hp + 12) = *reinterpret_cast<const float2*>(hn + 12);
}

// ---------------------------------------------------------------------------
// Persistent main kernel: one CTA = 28 batch rows; layers software-pipelined
// over stages (L_l at stage s handles timestep s-l).  One barrier per stage.
// 147 CTAs fill 147 of 148 SMs in a single wave.
// ---------------------------------------------------------------------------
__global__ void __launch_bounds__(NTHREADS, 1)
lstm_main(const float* __restrict__ x,
          const float* __restrict__ fcw,
          const float* __restrict__ fcb,
          float* __restrict__ out)
{
    extern __shared__ float sm[];

    const int tid  = threadIdx.x;
    const int w    = tid >> 5;
    const int lane = tid & 31;
    const int b0   = blockIdx.x * MTILE;

    // warp -> (layer, local index): balances FFMA2 load across SMSPs
    const int wlayerA[16] = {1,0,0,0, 1,0,0,0, 2,1,1,1, 3,2,3,2};
    const int wlocA[16]   = {0,0,1,2, 1,3,4,5, 0,2,3,4, 0,1,1,2};
    const int lyr = wlayerA[w];
    const int loc = wlocA[w];
    const int j    = loc * 16 + (lane >> 1);
    const int half = lane & 1;

    const int HHt[4] = {90, 66, 48, 24};
    const int BOt[4] = {0, 360, 624, 816};
    const int HH = HHt[lyr];
    const bool on = (j < HH);

    float4 bias = make_float4(0.f, 0.f, 0.f, 0.f);
    if (on) {
        const int BO = BOt[lyr];
        bias = make_float4(g_Bias[BO + j], g_Bias[BO + HH + j],
                           g_Bias[BO + 2 * HH + j], g_Bias[BO + 3 * HH + j]);
    }

    // stage L2/L3 weights into smem
    {
        const float4* gw4 = reinterpret_cast<const float4*>(g_WT);
        float4* w2 = reinterpret_cast<float4*>(sm + WL2_OFF);
        float4* w3 = reinterpret_cast<float4*>(sm + WL3_OFF);
        for (int i = tid; i < 5472; i += NTHREADS) w2[i] = gw4[24156 + i];
        for (int i = tid; i < 1728; i += NTHREADS) w3[i] = gw4[29628 + i];
    }
    // zero both state parities (includes pad cols)
    for (int i = tid; i < 2 * PSTRIDE; i += NTHREADS) sm[i] = 0.0f;

    // weight pointer for this thread's layer (float4 units, element k at wj[k*HH])
    const float4* gw = reinterpret_cast<const float4*>(g_WT);
    const float4* wj;
    if      (lyr == 0) wj = gw + j;
    else if (lyr == 1) wj = gw + 13860 + j;
    else if (lyr == 2) wj = reinterpret_cast<const float4*>(sm + WL2_OFF) + j;
    else               wj = reinterpret_cast<const float4*>(sm + WL3_OFF) + j;

    // x staging: warp w covers x feature rows 4w..4w+3; lane = batch row in tile.
    // batch col in S: rows 0..13 -> cols 0..13, rows 14..27 -> cols 16..29.
    const bool xlane = (lane < MTILE);
    const int  bidx  = b0 + lane;
    const int  bcl   = (bidx < Bsz) ? bidx : (Bsz - 1);   // clamp for last CTA
    const int  xcol  = (lane < 14) ? lane : lane + 2;
    const float* xrow = x + (size_t)bcl * Tlen * IND + 4 * w;

    {
        float4 xv = *reinterpret_cast<const float4*>(xrow);
        float* p1 = sm + PSTRIDE;
        if (xlane) {
            p1[(4 * w + 0) * SDIM + xcol] = xv.x;
            p1[(4 * w + 1) * SDIM + xcol] = xv.y;
            p1[(4 * w + 2) * SDIM + xcol] = xv.z;
            p1[(4 * w + 3) * SDIM + xcol] = xv.w;
        }
    }
    __syncthreads();

    unsigned long long c[NPAIR];
#pragma unroll
    for (int p = 0; p < NPAIR; ++p) c[p] = 0ull;

    for (int s = 0; s < NSTAGES; ++s) {
        const float* pin  = sm + ((s + 1) & 1) * PSTRIDE;  // == (s-1)&1
        float*       pout = sm + (s & 1) * PSTRIDE;

        // prefetch next x tile (goes to pout's x rows: parity s&1 read at s+1)
        float4 xv;
        const bool stx = (s < Tlen - 1);
        if (stx) xv = *reinterpret_cast<const float4*>(xrow + (size_t)(s + 1) * IND);

        const bool act = on && (s >= lyr) && (s - lyr < Tlen);
        if (act) {
            if      (lyr == 0) do_layer<90, 154,   0,  64, true >(bias, wj, pin, pout, c, j, half);
            else if (lyr == 1) do_layer<66, 156,  64, 154, true >(bias, wj, pin, pout, c, j, half);
            else if (lyr == 2) do_layer<48, 114, 154, 220, false>(bias, wj, pin, pout, c, j, half);
            else               do_layer<24,  72, 220, 268, false>(bias, wj, pin, pout, c, j, half);
        }

        if (stx && xlane) {
            pout[(4 * w + 0) * SDIM + xcol] = xv.x;
            pout[(4 * w + 1) * SDIM + xcol] = xv.y;
            pout[(4 * w + 2) * SDIM + xcol] = xv.z;
            pout[(4 * w + 3) * SDIM + xcol] = xv.w;
        }
        __syncthreads();
    }

    // h4[T-1] written at stage 514 -> parity 0
    if (tid < MTILE && b0 + tid < Bsz) {
        const int col = (tid < 14) ? tid : tid + 2;
        float acc = fcb[0];
#pragma unroll
        for (int jj = 0; jj < 24; ++jj)
            acc += sm[(H4OFF + jj) * SDIM + col] * fcw[jj];
        out[b0 + tid] = acc;
    }
}

// ---------------------------------------------------------------------------
extern "C" void kernel_launch(void* const* d_in, const int* in_sizes, int n_in,
                              void* d_out, int out_size)
{
    (void)in_sizes; (void)n_in; (void)out_size;
    const float* x    = (const float*)d_in[0];
    const float* Wih1 = (const float*)d_in[1];
    const float* Whh1 = (const float*)d_in[2];
    const float* bih1 = (const float*)d_in[3];
    const float* bhh1 = (const float*)d_in[4];
    const float* Wih2 = (const float*)d_in[5];
    const float* Whh2 = (const float*)d_in[6];
    const float* bih2 = (const float*)d_in[7];
    const float* bhh2 = (const float*)d_in[8];
    const float* Wih3 = (const float*)d_in[9];
    const float* Whh3 = (const float*)d_in[10];
    const float* bih3 = (const float*)d_in[11];
    const float* bhh3 = (const float*)d_in[12];
    const float* Wih4 = (const float*)d_in[13];
    const float* Whh4 = (const float*)d_in[14];
    const float* bih4 = (const float*)d_in[15];
    const float* bhh4 = (const float*)d_in[16];
    const float* fcw  = (const float*)d_in[17];
    const float* fcb  = (const float*)d_in[18];

    static bool attr_done = false;
    if (!attr_done) {
        cudaFuncSetAttribute(lstm_main,
                             cudaFuncAttributeMaxDynamicSharedMemorySize,
                             SMEM_BYTES);
        attr_done = true;
    }

    const int prep_total = WT_TOTAL + B_TOTAL;
    prep_kernel<<<(prep_total + 255) / 256, 256>>>(
        Wih1, Whh1, bih1, bhh1, Wih2, Whh2, bih2, bhh2,
        Wih3, Whh3, bih3, bhh3, Wih4, Whh4, bih4, bhh4);

    lstm_main<<<NBLOCKS, NTHREADS, SMEM_BYTES>>>(x, fcw, fcb, (float*)d_out);
}